// round 13
// baseline (speedup 1.0000x reference)
#include <cuda_runtime.h>

// LocallyConnected1d: out[b,o,l] = sum_{c,k} x[b,c,l+k]*w[o,c,l,k] + bias[o,l]
// B=32, Cin=128, Cout=128, L=2048, K=3, S=1, W=2050, fp32.
//
// R13: fills moved to the async-bulk engine (cp.async.bulk + mbarrier
// complete_tx). x is pre-transposed AND pre-swizzled (chunk ^= w&7) in the
// pre-pass, so each stage's X tile is 4 contiguous 4352B runs; W is 64x384B
// runs. 68 bulk ops/stage issued by threads 0..67; compute warps carry zero
// fill work. Compute core (f32x2 packed FMA, 2x LDS.128 swizzled x reads,
// stride-3 w reads) = R12 verbatim.

#define CIN     128
#define COUT    128
#define LOUT    2048
#define KW      3
#define WIN     2050

#define L_TILE  32
#define O_TILE  16
#define CC      4                     // Cin per pipeline stage
#define NST     (CIN / CC)            // 32 stages
#define NTHREADS 256

#define X_CI_BYTES 4352               // 34 w-rows * 128B, contiguous in g_xp
#define W_ROW_BYTES 384               // 96 floats per (oi,ci)
#define STAGE_X (CC * 34 * 32)        // 4352 floats
#define STAGE_F (STAGE_X + CC * O_TILE * 96)  // 10496 floats
#define STAGE_BYTES (STAGE_F * 4)     // 41984 B (= 4*4352 + 64*384)
#define SMEM_BYTES (1024 + 2 * STAGE_BYTES)   // mbarriers + 2 buffers

typedef unsigned long long u64;

// x transposed to [c][w][b] with the 16B-chunk swizzle (chunk ^= w&7)
// PRE-APPLIED, so smem fills are plain contiguous bulk copies.
__device__ __align__(128) float g_xp[CIN * WIN * 32];

static __device__ __forceinline__ u64 pack_dup(float a) {
    u64 r; asm("mov.b64 %0, {%1, %1};" : "=l"(r) : "f"(a)); return r;
}
static __device__ __forceinline__ void unpack2(u64 v, float& a, float& b) {
    asm("mov.b64 {%0, %1}, %2;" : "=f"(a), "=f"(b) : "l"(v));
}
static __device__ __forceinline__ void ffma2(u64& d, u64 a, u64 b) {
    asm("fma.rn.f32x2 %0, %1, %2, %0;" : "+l"(d) : "l"(a), "l"(b));
}
static __device__ __forceinline__ unsigned smem_u32(const void* p) {
    unsigned r;
    asm("{ .reg .u64 t; cvta.to.shared.u64 t, %1; cvt.u32.u64 %0, t; }"
        : "=r"(r) : "l"(p));
    return r;
}
static __device__ __forceinline__ void mbar_init(unsigned m, unsigned cnt) {
    asm volatile("mbarrier.init.shared.b64 [%0], %1;" :: "r"(m), "r"(cnt) : "memory");
}
static __device__ __forceinline__ void mbar_expect_tx(unsigned m, unsigned bytes) {
    asm volatile("mbarrier.arrive.expect_tx.shared.b64 _, [%0], %1;"
                 :: "r"(m), "r"(bytes) : "memory");
}
static __device__ __forceinline__ void mbar_wait(unsigned m, unsigned parity) {
    asm volatile(
        "{\n\t.reg .pred P;\n"
        "W_%=:\n\t"
        "mbarrier.try_wait.parity.acquire.cta.shared::cta.b64 P, [%0], %1, 0x989680;\n\t"
        "@!P bra W_%=;\n\t"
        "}" :: "r"(m), "r"(parity) : "memory");
}
static __device__ __forceinline__ void bulk_g2s(unsigned dst, const float* src,
                                                unsigned bytes, unsigned mbar) {
    asm volatile(
        "cp.async.bulk.shared::cluster.global.mbarrier::complete_tx::bytes "
        "[%0], [%1], %2, [%3];"
        :: "r"(dst), "l"(src), "r"(bytes), "r"(mbar) : "memory");
}

// -------- pre-pass: x[b][c][w] -> g_xp[c][w][chunk^(w&7)][b&3] ------------
__global__ void __launch_bounds__(256, 4)
transpose_x_kernel(const float* __restrict__ x)
{
    __shared__ float t[32][33];
    const int c  = blockIdx.y;
    const int w0 = blockIdx.x * 32;
    const int tx = threadIdx.x & 31;      // b on write side
    const int ty = threadIdx.x >> 5;

    #pragma unroll
    for (int i = 0; i < 4; i++) {             // read coalesced over w
        int b = ty + i * 8;
        int w = w0 + tx;
        t[b][tx] = (w < WIN) ? x[((long)b * CIN + c) * WIN + w] : 0.f;
    }
    __syncthreads();
    #pragma unroll
    for (int i = 0; i < 4; i++) {             // write coalesced over b
        int w = w0 + ty + i * 8;
        if (w < WIN) {
            int p = ((((tx >> 2) ^ (w & 7)) << 2) | (tx & 3));  // swizzled b
            g_xp[((long)c * WIN + w) * 32 + p] = t[tx][ty + i * 8];
        }
    }
}

// ------------------------------- main --------------------------------------
__global__ void __launch_bounds__(NTHREADS, 2)
lc1d_kernel(const float* __restrict__ wgt,
            const float* __restrict__ bias,
            float* __restrict__ out)
{
    extern __shared__ float smem[];
    const unsigned sb  = smem_u32(smem);
    const unsigned mb0 = sb;                  // full[0]
    const unsigned mb1 = sb + 8;              // full[1]
    const unsigned bufb = sb + 1024;          // buffers base (1024B aligned)
    float* bufs = smem + 256;                 // same, as float*

    const int tid  = threadIdx.x;
    const int lane = tid & 31;            // local l index (compute)
    const int warp = tid >> 5;
    const int bp0  = (warp & 3) * 4;      // b-pair group start (compute)
    const int og   = (warp >> 2) * 8;     // o group start (compute)
    const int o0   = blockIdx.x * O_TILE; // o-major raster (x L2 reuse)
    const int l0   = blockIdx.y * L_TILE;

    // ---- bulk-fill state: thread t<64 owns W row (oi=t>>2, ci=t&3);
    //      threads 64..67 own X run ci = t-64. Hoisted; one add per stage.
    const float* src = nullptr;
    unsigned dst_off = 0, cp_bytes = 0;
    long adv = 0;
    if (tid < 64) {
        const int oi = tid >> 2, ci = tid & 3;
        src      = wgt + ((long)((o0 + oi) * CIN + ci)) * (LOUT * KW) + l0 * KW;
        dst_off  = (unsigned)(STAGE_X * 4 + tid * W_ROW_BYTES);
        cp_bytes = W_ROW_BYTES;
        adv      = (long)CC * LOUT * KW;
    } else if (tid < 68) {
        const int ci = tid - 64;
        src      = g_xp + ((long)ci * WIN + l0) * 32;
        dst_off  = (unsigned)(ci * X_CI_BYTES);
        cp_bytes = X_CI_BYTES;
        adv      = (long)CC * WIN * 32;
    }

    u64 acc[4][8];
    #pragma unroll
    for (int p = 0; p < 4; p++)
        #pragma unroll
        for (int o = 0; o < 8; o++) acc[p][o] = 0ull;

    // ---- prologue: init barriers, issue stage 0 ----
    if (tid == 0) { mbar_init(mb0, 1); mbar_init(mb1, 1); }
    __syncthreads();
    if (tid == 0) mbar_expect_tx(mb0, STAGE_BYTES);
    if (tid < 68) { bulk_g2s(bufb + dst_off, src, cp_bytes, mb0); src += adv; }

    const int C0 = bp0 >> 1;              // logical 16B chunk of bp0,bp0+1
    #pragma unroll 1
    for (int s = 0; s < NST; s++) {
        mbar_wait((s & 1) ? mb1 : mb0, (s >> 1) & 1);   // stage s data ready
        __syncthreads();                   // compute(s-1) done -> buf free

        if (s + 1 < NST) {                 // fill s+1; rides async engine
            const unsigned mbn = ((s + 1) & 1) ? mb1 : mb0;
            if (tid == 0) mbar_expect_tx(mbn, STAGE_BYTES);
            if (tid < 68) {
                bulk_g2s(bufb + ((s + 1) & 1) * STAGE_BYTES + dst_off,
                         src, cp_bytes, mbn);
                src += adv;
            }
        }

        const float* Xb = bufs + (s & 1) * STAGE_F;
        const float* Wb = Xb + STAGE_X;
        const float4* X4 = reinterpret_cast<const float4*>(Xb);

        #pragma unroll
        for (int ci = 0; ci < CC; ci++) {
            // hoist all 6 x LDS.128 for this ci (latency amortized once)
            ulonglong2 va[KW], vb[KW];
            #pragma unroll
            for (int k = 0; k < KW; k++) {
                const int w  = lane + k;
                const int w7 = w & 7;                  // swizzle: abs-w based
                const int rb = (ci * 34 + w) * 8;
                va[k] = *reinterpret_cast<const ulonglong2*>(
                            X4 + rb + (C0 ^ w7));
                vb[k] = *reinterpret_cast<const ulonglong2*>(
                            X4 + rb + ((C0 + 1) ^ w7));
            }
            #pragma unroll
            for (int k = 0; k < KW; k++) {
                // W layout [oi][ci][96]; lane*3+k coprime with 32 banks
                const float* wp = Wb + ci * 96 + lane * KW + k;
                #pragma unroll
                for (int oi = 0; oi < 8; oi++) {
                    u64 wv = pack_dup(wp[(og + oi) * (4 * 96)]);
                    ffma2(acc[0][oi], va[k].x, wv);
                    ffma2(acc[1][oi], va[k].y, wv);
                    ffma2(acc[2][oi], vb[k].x, wv);
                    ffma2(acc[3][oi], vb[k].y, wv);
                }
            }
        }
    }

    // epilogue: bias + coalesced stores (l-contiguous)
    const int b0 = (warp & 3) * 8;
    #pragma unroll
    for (int oi = 0; oi < 8; oi++) {
        int o = o0 + og + oi;
        float bv = bias[o * LOUT + l0 + lane];
        #pragma unroll
        for (int p = 0; p < 4; p++) {
            float f0, f1;
            unpack2(acc[p][oi], f0, f1);
            int b = b0 + 2 * p;
            out[(b * COUT + o) * LOUT + l0 + lane]       = f0 + bv;
            out[((b + 1) * COUT + o) * LOUT + l0 + lane] = f1 + bv;
        }
    }
}

extern "C" void kernel_launch(void* const* d_in, const int* in_sizes, int n_in,
                              void* d_out, int out_size)
{
    const float* x    = (const float*)d_in[0];
    const float* wgt  = (const float*)d_in[1];
    const float* bias = (const float*)d_in[2];
    float* out        = (float*)d_out;

    cudaFuncSetAttribute(lc1d_kernel,
                         cudaFuncAttributeMaxDynamicSharedMemorySize, SMEM_BYTES);

    dim3 tgrid((WIN + 31) / 32, CIN);          // (65, 128)
    transpose_x_kernel<<<tgrid, 256>>>(x);

    dim3 grid(COUT / O_TILE, LOUT / L_TILE);   // (8, 64): o fastest
    lc1d_kernel<<<grid, NTHREADS, SMEM_BYTES>>>(wgt, bias, out);
}

// round 14
// speedup vs baseline: 1.6648x; 1.6648x over previous
#include <cuda_runtime.h>

// LocallyConnected1d: out[b,o,l] = sum_{c,k} x[b,c,l+k]*w[o,c,l,k] + bias[o,l]
// B=32, Cin=128, Cout=128, L=2048, K=3, S=1, W=2050, fp32.
//
// R14 hybrid fills: X = 4x 4352B cp.async.bulk (large contiguous runs in
// pre-swizzled g_xp; mbarrier complete_tx) — async engine's sweet spot.
// W = 64x 384B via cp.async.16 spread over all 8 warps (8 rows each,
// compile-time offsets) — LDGSTS's sweet spot. R13's all-bulk W (64 tiny
// ops/stage) choked the async engine; this keeps each mover where it wins.
// Compute core (f32x2 FMA, swizzled 2x LDS.128 x, stride-3 w) unchanged.

#define CIN     128
#define COUT    128
#define LOUT    2048
#define KW      3
#define WIN     2050

#define L_TILE  32
#define O_TILE  16
#define CC      4                     // Cin per pipeline stage
#define NST     (CIN / CC)            // 32 stages
#define NTHREADS 256

#define X_CI_BYTES 4352               // 34 w-rows * 128B, contiguous in g_xp
#define X_BYTES    (CC * X_CI_BYTES)  // 17408 B per stage
#define W_ROW_BYTES 384               // 96 floats per (oi,ci) row
#define STAGE_X (CC * 34 * 32)        // 4352 floats
#define STAGE_F (STAGE_X + CC * O_TILE * 96)  // 10496 floats
#define STAGE_BYTES (STAGE_F * 4)     // 41984 B
#define SMEM_BYTES (1024 + 2 * STAGE_BYTES)   // mbarriers + 2 buffers

typedef unsigned long long u64;

// x transposed to [c][w][b] with the 16B-chunk swizzle (chunk ^= w&7)
// PRE-APPLIED, so X smem fills are plain contiguous bulk copies.
__device__ __align__(128) float g_xp[CIN * WIN * 32];

static __device__ __forceinline__ u64 pack_dup(float a) {
    u64 r; asm("mov.b64 %0, {%1, %1};" : "=l"(r) : "f"(a)); return r;
}
static __device__ __forceinline__ void unpack2(u64 v, float& a, float& b) {
    asm("mov.b64 {%0, %1}, %2;" : "=f"(a), "=f"(b) : "l"(v));
}
static __device__ __forceinline__ void ffma2(u64& d, u64 a, u64 b) {
    asm("fma.rn.f32x2 %0, %1, %2, %0;" : "+l"(d) : "l"(a), "l"(b));
}
static __device__ __forceinline__ unsigned smem_u32(const void* p) {
    unsigned r;
    asm("{ .reg .u64 t; cvta.to.shared.u64 t, %1; cvt.u32.u64 %0, t; }"
        : "=r"(r) : "l"(p));
    return r;
}
static __device__ __forceinline__ void mbar_init(unsigned m, unsigned cnt) {
    asm volatile("mbarrier.init.shared.b64 [%0], %1;" :: "r"(m), "r"(cnt) : "memory");
}
static __device__ __forceinline__ void mbar_expect_tx(unsigned m, unsigned bytes) {
    asm volatile("mbarrier.arrive.expect_tx.shared.b64 _, [%0], %1;"
                 :: "r"(m), "r"(bytes) : "memory");
}
static __device__ __forceinline__ void mbar_wait(unsigned m, unsigned parity) {
    asm volatile(
        "{\n\t.reg .pred P;\n"
        "W_%=:\n\t"
        "mbarrier.try_wait.parity.acquire.cta.shared::cta.b64 P, [%0], %1, 0x989680;\n\t"
        "@!P bra W_%=;\n\t"
        "}" :: "r"(m), "r"(parity) : "memory");
}
static __device__ __forceinline__ void bulk_g2s(unsigned dst, const float* src,
                                                unsigned bytes, unsigned mbar) {
    asm volatile(
        "cp.async.bulk.shared::cluster.global.mbarrier::complete_tx::bytes "
        "[%0], [%1], %2, [%3];"
        :: "r"(dst), "l"(src), "r"(bytes), "r"(mbar) : "memory");
}
static __device__ __forceinline__ void cpa16(unsigned d, const float* s) {
    asm volatile("cp.async.cg.shared.global [%0], [%1], 16;" :: "r"(d), "l"(s));
}
#define CP_COMMIT() asm volatile("cp.async.commit_group;" ::: "memory")
#define CP_WAIT0()  asm volatile("cp.async.wait_group 0;" ::: "memory")

// -------- pre-pass: x[b][c][w] -> g_xp[c][w][chunk^(w&7)][b&3] ------------
__global__ void __launch_bounds__(256, 4)
transpose_x_kernel(const float* __restrict__ x)
{
    __shared__ float t[32][33];
    const int c  = blockIdx.y;
    const int w0 = blockIdx.x * 32;
    const int tx = threadIdx.x & 31;      // b on write side
    const int ty = threadIdx.x >> 5;

    #pragma unroll
    for (int i = 0; i < 4; i++) {             // read coalesced over w
        int b = ty + i * 8;
        int w = w0 + tx;
        t[b][tx] = (w < WIN) ? x[((long)b * CIN + c) * WIN + w] : 0.f;
    }
    __syncthreads();
    #pragma unroll
    for (int i = 0; i < 4; i++) {             // write coalesced over b
        int w = w0 + ty + i * 8;
        if (w < WIN) {
            int p = ((((tx >> 2) ^ (w & 7)) << 2) | (tx & 3));  // swizzled b
            g_xp[((long)c * WIN + w) * 32 + p] = t[tx][ty + i * 8];
        }
    }
}

// ------------------------------- main --------------------------------------
__global__ void __launch_bounds__(NTHREADS, 2)
lc1d_kernel(const float* __restrict__ wgt,
            const float* __restrict__ bias,
            float* __restrict__ out)
{
    extern __shared__ float smem[];
    const unsigned sb  = smem_u32(smem);
    const unsigned mb0 = sb;                  // X full[0]
    const unsigned mb1 = sb + 8;              // X full[1]
    const unsigned bufb = sb + 1024;          // buffers base (128B aligned)
    float* bufs = smem + 256;

    const int tid  = threadIdx.x;
    const int lane = tid & 31;            // local l index (compute)
    const int warp = tid >> 5;
    const int bp0  = (warp & 3) * 4;      // b-pair group start (compute)
    const int og   = (warp >> 2) * 8;     // o group start (compute)
    const int o0   = blockIdx.x * O_TILE; // o-major raster (x L2 reuse)
    const int l0   = blockIdx.y * L_TILE;

    // ---- X bulk state: threads 64..67 own run ci = tid-64 (4 x 4352B) ----
    const float* xsrc = nullptr;
    unsigned xdst = 0;
    if (tid >= 64 && tid < 68) {
        const int ci = tid - 64;
        xsrc = g_xp + ((long)ci * WIN + l0) * 32;
        xdst = (unsigned)(ci * X_CI_BYTES);
    }

    // ---- W cp.async state: warp w owns rows r = warp*8 + i_, i_=0..7;
    //      row r: oi = r>>2 = warp*2 + (i_>>2), ci = i_&3. Row offsets from
    //      the i_=0 row are compile-time constants. lanes 0..23 sweep 384B.
    const float* wsrc = wgt + ((long)((o0 + warp * 2) * CIN)) * (LOUT * KW)
                            + l0 * KW + lane * 4;
    const unsigned wdst = (unsigned)(STAGE_X * 4 + warp * 8 * W_ROW_BYTES
                                     + lane * 16);

    u64 acc[4][8];
    #pragma unroll
    for (int p = 0; p < 4; p++)
        #pragma unroll
        for (int o = 0; o < 8; o++) acc[p][o] = 0ull;

    #define ISSUE_X(buf, mb) do {                                           \
        if (tid == 64) mbar_expect_tx(mb, X_BYTES);                         \
        if (tid >= 64 && tid < 68)                                          \
            bulk_g2s(bufb + (unsigned)(buf) * STAGE_BYTES + xdst,           \
                     xsrc, X_CI_BYTES, mb);                                 \
        if (tid >= 64 && tid < 68) xsrc += (long)CC * WIN * 32;             \
    } while (0)

    #define ISSUE_W(buf) do {                                               \
        if (lane < 24) {                                                    \
            unsigned dW_ = bufb + (unsigned)(buf) * STAGE_BYTES + wdst;     \
            _Pragma("unroll")                                               \
            for (int i_ = 0; i_ < 8; i_++)                                  \
                cpa16(dW_ + (unsigned)(i_ * W_ROW_BYTES),                   \
                      wsrc + (long)((i_ >> 2) * CIN + (i_ & 3))             \
                           * (LOUT * KW));                                  \
        }                                                                   \
        wsrc += (long)CC * LOUT * KW;                                       \
        CP_COMMIT();                                                        \
    } while (0)

    // ---- prologue ----
    if (tid == 0) { mbar_init(mb0, 1); mbar_init(mb1, 1); }
    __syncthreads();
    ISSUE_X(0, mb0);
    ISSUE_W(0);

    const int C0 = bp0 >> 1;              // logical 16B chunk of bp0,bp0+1
    #pragma unroll 1
    for (int s = 0; s < NST; s++) {
        CP_WAIT0();                        // own W copies for stage s done
        mbar_wait((s & 1) ? mb1 : mb0, (s >> 1) & 1);   // X for stage s done
        __syncthreads();                   // all visible; buffer s-1 free

        if (s + 1 < NST) {                 // fill s+1 into the freed buffer
            ISSUE_X((s + 1) & 1, ((s + 1) & 1) ? mb1 : mb0);
            ISSUE_W((s + 1) & 1);
        }

        const float* Xb = bufs + (s & 1) * STAGE_F;
        const float* Wb = Xb + STAGE_X;
        const float4* X4 = reinterpret_cast<const float4*>(Xb);

        #pragma unroll
        for (int ci = 0; ci < CC; ci++) {
            // hoist all 6 x LDS.128 for this ci (latency amortized once)
            ulonglong2 va[KW], vb[KW];
            #pragma unroll
            for (int k = 0; k < KW; k++) {
                const int w  = lane + k;
                const int w7 = w & 7;
                const int rb = (ci * 34 + w) * 8;
                va[k] = *reinterpret_cast<const ulonglong2*>(
                            X4 + rb + (C0 ^ w7));
                vb[k] = *reinterpret_cast<const ulonglong2*>(
                            X4 + rb + ((C0 + 1) ^ w7));
            }
            #pragma unroll
            for (int k = 0; k < KW; k++) {
                // W layout [oi][ci][96]; lane*3+k coprime with 32 banks
                const float* wp = Wb + ci * 96 + lane * KW + k;
                #pragma unroll
                for (int oi = 0; oi < 8; oi++) {
                    u64 wv = pack_dup(wp[(og + oi) * (4 * 96)]);
                    ffma2(acc[0][oi], va[k].x, wv);
                    ffma2(acc[1][oi], va[k].y, wv);
                    ffma2(acc[2][oi], vb[k].x, wv);
                    ffma2(acc[3][oi], vb[k].y, wv);
                }
            }
        }
    }

    // epilogue: bias + coalesced stores (l-contiguous)
    const int b0 = (warp & 3) * 8;
    #pragma unroll
    for (int oi = 0; oi < 8; oi++) {
        int o = o0 + og + oi;
        float bv = bias[o * LOUT + l0 + lane];
        #pragma unroll
        for (int p = 0; p < 4; p++) {
            float f0, f1;
            unpack2(acc[p][oi], f0, f1);
            int b = b0 + 2 * p;
            out[(b * COUT + o) * LOUT + l0 + lane]       = f0 + bv;
            out[((b + 1) * COUT + o) * LOUT + l0 + lane] = f1 + bv;
        }
    }
}

extern "C" void kernel_launch(void* const* d_in, const int* in_sizes, int n_in,
                              void* d_out, int out_size)
{
    const float* x    = (const float*)d_in[0];
    const float* wgt  = (const float*)d_in[1];
    const float* bias = (const float*)d_in[2];
    float* out        = (float*)d_out;

    cudaFuncSetAttribute(lc1d_kernel,
                         cudaFuncAttributeMaxDynamicSharedMemorySize, SMEM_BYTES);

    dim3 tgrid((WIN + 31) / 32, CIN);          // (65, 128)
    transpose_x_kernel<<<tgrid, 256>>>(x);

    dim3 grid(COUT / O_TILE, LOUT / L_TILE);   // (8, 64): o fastest
    lc1d_kernel<<<grid, NTHREADS, SMEM_BYTES>>>(wgt, bias, out);
}

// round 15
// speedup vs baseline: 1.7815x; 1.0701x over previous
#include <cuda_runtime.h>

// LocallyConnected1d: out[b,o,l] = sum_{c,k} x[b,c,l+k]*w[o,c,l,k] + bias[o,l]
// B=32, Cin=128, Cout=128, L=2048, K=3, S=1, W=2050, fp32.
//
// R15 = R12 (best: pre-transposed x, 16B cp.async fills, chunk-swizzled X
// smem, f32x2 FMA, hoisted x LDS.128) with BALANCED fills: every warp
// issues 4-5 X ops + 8 W ops (max burst 13 vs R12's 16 on W-warps).

#define CIN     128
#define COUT    128
#define LOUT    2048
#define KW      3
#define WIN     2050

#define L_TILE  32
#define O_TILE  16
#define CC      4                     // Cin per pipeline stage
#define NST     (CIN / CC)            // 32 stages
#define NTHREADS 256

#define STAGE_X (CC * 34 * 32)        // 4352 floats ([ci][w][32b], swizzled)
#define STAGE_W (CC * O_TILE * 96)    // 6144 floats ([ci][oi][96])
#define STAGE_F (STAGE_X + STAGE_W)   // 10496 floats
#define STAGE_BYTES (STAGE_F * 4)     // 41984 B
#define SMEM_BYTES (2 * STAGE_BYTES)  // 83968 B -> 2 blocks/SM

typedef unsigned long long u64;

// x transposed to [c][w][b]: fill reads become 128B-contiguous rows.
__device__ float g_xp[CIN * WIN * 32];

static __device__ __forceinline__ u64 pack_dup(float a) {
    u64 r; asm("mov.b64 %0, {%1, %1};" : "=l"(r) : "f"(a)); return r;
}
static __device__ __forceinline__ void unpack2(u64 v, float& a, float& b) {
    asm("mov.b64 {%0, %1}, %2;" : "=f"(a), "=f"(b) : "l"(v));
}
static __device__ __forceinline__ void ffma2(u64& d, u64 a, u64 b) {
    asm("fma.rn.f32x2 %0, %1, %2, %0;" : "+l"(d) : "l"(a), "l"(b));
}
static __device__ __forceinline__ unsigned smem_u32(const void* p) {
    unsigned r;
    asm("{ .reg .u64 t; cvta.to.shared.u64 t, %1; cvt.u32.u64 %0, t; }"
        : "=r"(r) : "l"(p));
    return r;
}
static __device__ __forceinline__ void cpa16(unsigned d, const float* s) {
    asm volatile("cp.async.cg.shared.global [%0], [%1], 16;" :: "r"(d), "l"(s));
}
static __device__ __forceinline__ void cpa16p(unsigned d, const float* s, bool p) {
    if (p) cpa16(d, s);
}
#define CP_COMMIT() asm volatile("cp.async.commit_group;" ::: "memory")
#define CP_WAIT0()  asm volatile("cp.async.wait_group 0;" ::: "memory")

// ---------------- pre-pass: x[b][c][w] -> g_xp[c][w][b] -------------------
__global__ void __launch_bounds__(256, 4)
transpose_x_kernel(const float* __restrict__ x)
{
    __shared__ float t[32][33];
    const int c  = blockIdx.y;
    const int w0 = blockIdx.x * 32;
    const int tx = threadIdx.x & 31;
    const int ty = threadIdx.x >> 5;

    #pragma unroll
    for (int i = 0; i < 4; i++) {            // read coalesced over w
        int b = ty + i * 8;
        int w = w0 + tx;
        t[b][tx] = (w < WIN) ? x[((long)b * CIN + c) * WIN + w] : 0.f;
    }
    __syncthreads();
    #pragma unroll
    for (int i = 0; i < 4; i++) {            // write coalesced over b
        int w = w0 + ty + i * 8;
        if (w < WIN)
            g_xp[((long)c * WIN + w) * 32 + tx] = t[tx][ty + i * 8];
    }
}

// ------------------------------- main --------------------------------------
__global__ void __launch_bounds__(NTHREADS, 2)
lc1d_kernel(const float* __restrict__ wgt,
            const float* __restrict__ bias,
            float* __restrict__ out)
{
    extern __shared__ float smem[];
    const unsigned sb = smem_u32(smem);

    const int tid  = threadIdx.x;
    const int lane = tid & 31;            // local l index (compute)
    const int warp = tid >> 5;
    const int bp0  = (warp & 3) * 4;      // b-pair group start (compute)
    const int og   = (warp >> 2) * 8;     // o group start (compute)
    const int o0   = blockIdx.x * O_TILE; // o-major raster (x L2 reuse)
    const int l0   = blockIdx.y * L_TILE;

    // ============ fill state: BALANCED across all 8 warps ================
    // X: warp owns ci = warp&3; lower half (warp<4) does ops i=0..3,
    //    upper half does i=4..7 + tail (w=32,33; lanes 0..15).
    //    op i: lane -> (w = i*4 + hi, chunk = lo8), 512B contiguous global;
    //    dst chunk swizzled by w&7 (dstE even-i, dstO odd-i).
    // W: warp owns rows (oi = warp*2 + (i>>2), ci = i&3), i=0..7;
    //    lanes 0..23 sweep each 96-float run as float4.
    const int xci  = warp & 3;
    const bool xup = (warp >> 2) != 0;    // which i-range this warp covers
    const int hi = lane >> 3, lo8 = lane & 7;

    const float* xsrc = g_xp + ((long)(xci * WIN) + l0 + hi) * 32 + lo8 * 4;
    const unsigned dstE = (unsigned)((xci * 34 + hi) * 32 + (lo8 ^ hi) * 4);
    const unsigned dstO = (unsigned)((xci * 34 + hi) * 32 + (lo8 ^ (hi + 4)) * 4);

    const float* wsrc = wgt + ((long)((o0 + warp * 2) * CIN)) * (LOUT * KW)
                            + l0 * KW + lane * 4;
    // dst row (oi,ci) = (ci*16 + oi)*96 floats; base at (0*16 + warp*2)
    const unsigned wdst = (unsigned)(STAGE_X + warp * 2 * 96 + lane * 4);

    u64 acc[4][8];
    #pragma unroll
    for (int p = 0; p < 4; p++)
        #pragma unroll
        for (int o = 0; o < 8; o++) acc[p][o] = 0ull;

    #define ISSUE(buf) do {                                                 \
        const unsigned base_ = sb + (unsigned)(buf) * STAGE_BYTES;          \
        /* ---- X: 4 ops (+tail) ---- */                                    \
        unsigned dE_ = base_ + dstE * 4u;                                   \
        unsigned dO_ = base_ + dstO * 4u;                                   \
        if (!xup) {                                                         \
            _Pragma("unroll")                                               \
            for (int i_ = 0; i_ < 4; i_++) {                                \
                unsigned d_ = ((i_ & 1) ? dO_ : dE_) + (unsigned)(i_ * 512);\
                cpa16(d_, xsrc + (long)i_ * 128);                           \
            }                                                               \
        } else {                                                            \
            _Pragma("unroll")                                               \
            for (int i_ = 4; i_ < 8; i_++) {                                \
                unsigned d_ = ((i_ & 1) ? dO_ : dE_) + (unsigned)(i_ * 512);\
                cpa16(d_, xsrc + (long)i_ * 128);                           \
            }                                                               \
            cpa16p(dE_ + 8u * 512u, xsrc + 8L * 128, lane < 16);            \
        }                                                                   \
        xsrc += (long)CC * WIN * 32;                                        \
        /* ---- W: 8 ops (lanes 0..23) ---- */                              \
        if (lane < 24) {                                                    \
            unsigned dW_ = base_ + wdst * 4u;                               \
            _Pragma("unroll")                                               \
            for (int i_ = 0; i_ < 8; i_++)                                  \
                cpa16(dW_ + (unsigned)((((i_ & 3) * 16 + (i_ >> 2)) * 96) * 4), \
                      wsrc + (long)((i_ >> 2) * CIN + (i_ & 3))             \
                           * (LOUT * KW));                                  \
        }                                                                   \
        wsrc += (long)CC * LOUT * KW;                                       \
        CP_COMMIT();                                                        \
    } while (0)

    // prologue: prefetch stage 0
    ISSUE(0);

    const int C0 = bp0 >> 1;              // logical 16B chunk of bp0,bp0+1
    #pragma unroll 1
    for (int s = 0; s < NST; s++) {
        CP_WAIT0();                        // stage s's fills complete
        __syncthreads();                   // visible block-wide; buf s-1 free

        if (s + 1 < NST) {                 // fill s+1; overlaps compute(s)
            ISSUE((s + 1) & 1);
        }

        const float* Xb = smem + (s & 1) * STAGE_F;
        const float* Wb = Xb + STAGE_X;
        const float4* X4 = reinterpret_cast<const float4*>(Xb);

        #pragma unroll
        for (int ci = 0; ci < CC; ci++) {
            // hoist all 6 x LDS.128 for this ci (latency amortized once)
            ulonglong2 va[KW], vb[KW];
            #pragma unroll
            for (int k = 0; k < KW; k++) {
                const int w  = lane + k;
                const int w7 = w & 7;
                const int rb = (ci * 34 + w) * 8;
                va[k] = *reinterpret_cast<const ulonglong2*>(
                            X4 + rb + (C0 ^ w7));
                vb[k] = *reinterpret_cast<const ulonglong2*>(
                            X4 + rb + ((C0 + 1) ^ w7));
            }
            #pragma unroll
            for (int k = 0; k < KW; k++) {
                // w: stride-3 lane addressing, coprime with 32 banks
                const float* wp = Wb + (ci * O_TILE + og) * 96 + lane * KW + k;
                #pragma unroll
                for (int oi = 0; oi < 8; oi++) {
                    u64 wv = pack_dup(wp[oi * 96]);
                    ffma2(acc[0][oi], va[k].x, wv);
                    ffma2(acc[1][oi], va[k].y, wv);
                    ffma2(acc[2][oi], vb[k].x, wv);
                    ffma2(acc[3][oi], vb[k].y, wv);
                }
            }
        }
    }

    // epilogue: bias + coalesced stores (l-contiguous)
    const int b0 = (warp & 3) * 8;
    #pragma unroll
    for (int oi = 0; oi < 8; oi++) {
        int o = o0 + og + oi;
        float bv = bias[o * LOUT + l0 + lane];
        #pragma unroll
        for (int p = 0; p < 4; p++) {
            float f0, f1;
            unpack2(acc[p][oi], f0, f1);
            int b = b0 + 2 * p;
            out[(b * COUT + o) * LOUT + l0 + lane]       = f0 + bv;
            out[((b + 1) * COUT + o) * LOUT + l0 + lane] = f1 + bv;
        }
    }
}

extern "C" void kernel_launch(void* const* d_in, const int* in_sizes, int n_in,
                              void* d_out, int out_size)
{
    const float* x    = (const float*)d_in[0];
    const float* wgt  = (const float*)d_in[1];
    const float* bias = (const float*)d_in[2];
    float* out        = (float*)d_out;

    cudaFuncSetAttribute(lc1d_kernel,
                         cudaFuncAttributeMaxDynamicSharedMemorySize, SMEM_BYTES);

    dim3 tgrid((WIN + 31) / 32, CIN);          // (65, 128)
    transpose_x_kernel<<<tgrid, 256>>>(x);

    dim3 grid(COUT / O_TILE, LOUT / L_TILE);   // (8, 64): o fastest
    lc1d_kernel<<<grid, NTHREADS, SMEM_BYTES>>>(wgt, bias, out);
}